// round 1
// baseline (speedup 1.0000x reference)
#include <cuda_runtime.h>

#define NN 50000
#define NE 500000
#define D 128
#define NL 4
#define NG 64
#define FIXEDDIM 10000
#define BNEPS 1e-5f

// ---------------- scratch (device globals: no allocation allowed) ----------
__device__ float g_h[NN * D];
__device__ float g_agg[NN * D];
__device__ float g_z1[NN * D];
__device__ float g_z2[NN * D];
__device__ int g_deg[NN];
__device__ int g_rowptr[NN + 1];
__device__ int g_cursor[NN];
__device__ int g_col[NE];
__device__ int g_starts[NG + 1];
__device__ double g_bsum[D];
__device__ double g_bsq[D];
__device__ float g_scale[D];
__device__ float g_shift[D];

// ---------------- setup kernels --------------------------------------------
__global__ void k_zero() {
    int i = blockIdx.x * blockDim.x + threadIdx.x;
    if (i < NN) g_deg[i] = 0;
    if (i < D) { g_bsum[i] = 0.0; g_bsq[i] = 0.0; }
}

__global__ void k_deg(const int* __restrict__ dst) {
    int e = blockIdx.x * blockDim.x + threadIdx.x;
    if (e < NE) atomicAdd(&g_deg[dst[e]], 1);
}

// exclusive prefix sum of g_deg -> g_rowptr (and cursor copy), single block
__global__ void k_scan() {
    __shared__ int sh[1024];
    int tid = threadIdx.x;
    int carry = 0;
    for (int base = 0; base < NN; base += 1024) {
        int i = base + tid;
        int v = (i < NN) ? g_deg[i] : 0;
        sh[tid] = v;
        __syncthreads();
        for (int off = 1; off < 1024; off <<= 1) {
            int t = (tid >= off) ? sh[tid - off] : 0;
            __syncthreads();
            sh[tid] += t;
            __syncthreads();
        }
        if (i < NN) {
            int ex = carry + sh[tid] - v;
            g_rowptr[i] = ex;
            g_cursor[i] = ex;
        }
        carry += sh[1023];
        __syncthreads();
    }
    if (tid == 0) g_rowptr[NN] = carry;
}

__global__ void k_fill(const int* __restrict__ src, const int* __restrict__ dst) {
    int e = blockIdx.x * blockDim.x + threadIdx.x;
    if (e < NE) {
        int pos = atomicAdd(&g_cursor[dst[e]], 1);
        g_col[pos] = src[e];
    }
}

// h = value_proj_w[feat_id] + b + deg_emb[min(deg,1000)]
__global__ void k_init(const int* __restrict__ feat_id,
                       const float4* __restrict__ w,
                       const float4* __restrict__ b,
                       const float4* __restrict__ demb) {
    int i = blockIdx.x * blockDim.x + threadIdx.x;  // NN*32 threads
    int v = i >> 5, j = i & 31;
    if (v >= NN) return;
    int fid = feat_id[v] % FIXEDDIM;
    int dg = g_deg[v];
    if (dg > 1000) dg = 1000;
    float4 a = w[fid * 32 + j];
    float4 bb = b[j];
    float4 dd = demb[dg * 32 + j];
    float4 r;
    r.x = a.x + bb.x + dd.x;
    r.y = a.y + bb.y + dd.y;
    r.z = a.z + bb.z + dd.z;
    r.w = a.w + bb.w + dd.w;
    ((float4*)g_h)[v * 32 + j] = r;
}

// ---------------- aggregation: agg[v] = h[v] + sum_{u in N(v)} h[u] --------
__global__ void k_agg() {
    int idx = blockIdx.x * blockDim.x + threadIdx.x;
    int v = idx >> 5, lane = idx & 31;
    if (v >= NN) return;
    const float4* h4 = (const float4*)g_h;
    float4 acc = h4[v * 32 + lane];
    int beg = g_rowptr[v], end = g_rowptr[v + 1];
    for (int j = beg; j < end; j++) {
        int s = g_col[j];
        float4 t = h4[s * 32 + lane];
        acc.x += t.x; acc.y += t.y; acc.z += t.z; acc.w += t.w;
    }
    ((float4*)g_agg)[v * 32 + lane] = acc;
}

// ---------------- fused GEMM (+optional input BN-affine+relu) + BN stats ---
// out[M,128] = act(A)[M,128] @ W[128,128] + bias;  act = relu(x*scale+shift)
// AS: 0 -> A = g_agg (raw), 1 -> A = g_z1 (apply affine)
// OS: 0 -> out = g_z1,       1 -> out = g_z2
template <bool AFFINE, int AS, int OS>
__global__ __launch_bounds__(256) void k_gemm(const float* __restrict__ W,
                                              const float* __restrict__ bias) {
    const float* __restrict__ A = (AS == 0) ? g_agg : g_z1;
    float* __restrict__ out = (OS == 0) ? g_z1 : g_z2;

    __shared__ float As[32][33];    // [row][k]
    __shared__ float Bs[32][128];   // [k][col]
    __shared__ float ssum[D], ssq[D];

    int tid = threadIdx.x;
    int rowBase = blockIdx.x * 32;
    int trow = tid >> 5;   // 0..7  (thread-row; one warp = one trow)
    int tcol = tid & 31;   // 0..31 (thread-col)

    float acc[4][4];
#pragma unroll
    for (int r = 0; r < 4; r++)
#pragma unroll
        for (int c = 0; c < 4; c++) acc[r][c] = 0.f;

    int lrow = tid >> 3;  // 0..31 row within A tile
    int lc4 = tid & 7;    // 0..7  float4 within k-chunk

#pragma unroll
    for (int kb = 0; kb < 4; kb++) {
        // --- load A tile (32 rows x 32 k), optionally affine+relu ---
        int arow = rowBase + lrow;
        int kglob = kb * 32 + lc4 * 4;
        float4 av = make_float4(0.f, 0.f, 0.f, 0.f);
        if (arow < NN) av = *(const float4*)&A[arow * D + kglob];
        if (AFFINE) {
            av.x = fmaxf(av.x * g_scale[kglob + 0] + g_shift[kglob + 0], 0.f);
            av.y = fmaxf(av.y * g_scale[kglob + 1] + g_shift[kglob + 1], 0.f);
            av.z = fmaxf(av.z * g_scale[kglob + 2] + g_shift[kglob + 2], 0.f);
            av.w = fmaxf(av.w * g_scale[kglob + 3] + g_shift[kglob + 3], 0.f);
            if (arow >= NN) av = make_float4(0.f, 0.f, 0.f, 0.f);
        }
        As[lrow][lc4 * 4 + 0] = av.x;
        As[lrow][lc4 * 4 + 1] = av.y;
        As[lrow][lc4 * 4 + 2] = av.z;
        As[lrow][lc4 * 4 + 3] = av.w;
        // --- load B tile (32 k x 128 cols) ---
#pragma unroll
        for (int i = 0; i < 4; i++) {
            int lin = tid + i * 256;
            int br = lin >> 5, bc4 = lin & 31;
            *(float4*)&Bs[br][bc4 * 4] = *(const float4*)&W[(kb * 32 + br) * D + bc4 * 4];
        }
        __syncthreads();
#pragma unroll
        for (int kk = 0; kk < 32; kk++) {
            float a0 = As[trow * 4 + 0][kk];
            float a1 = As[trow * 4 + 1][kk];
            float a2 = As[trow * 4 + 2][kk];
            float a3 = As[trow * 4 + 3][kk];
            float4 b = *(const float4*)&Bs[kk][tcol * 4];
            acc[0][0] += a0 * b.x; acc[0][1] += a0 * b.y; acc[0][2] += a0 * b.z; acc[0][3] += a0 * b.w;
            acc[1][0] += a1 * b.x; acc[1][1] += a1 * b.y; acc[1][2] += a1 * b.z; acc[1][3] += a1 * b.w;
            acc[2][0] += a2 * b.x; acc[2][1] += a2 * b.y; acc[2][2] += a2 * b.z; acc[2][3] += a2 * b.w;
            acc[3][0] += a3 * b.x; acc[3][1] += a3 * b.y; acc[3][2] += a3 * b.z; acc[3][3] += a3 * b.w;
        }
        __syncthreads();
    }

    // --- epilogue: +bias, store, accumulate BN stats ---
    if (tid < D) { ssum[tid] = 0.f; ssq[tid] = 0.f; }
    __syncthreads();

    float4 bv = *(const float4*)&bias[tcol * 4];
    float s0 = 0.f, s1 = 0.f, s2 = 0.f, s3 = 0.f;
    float q0 = 0.f, q1 = 0.f, q2 = 0.f, q3 = 0.f;
#pragma unroll
    for (int r = 0; r < 4; r++) {
        int row = rowBase + trow * 4 + r;
        if (row < NN) {
            float4 v;
            v.x = acc[r][0] + bv.x;
            v.y = acc[r][1] + bv.y;
            v.z = acc[r][2] + bv.z;
            v.w = acc[r][3] + bv.w;
            *(float4*)&out[row * D + tcol * 4] = v;
            s0 += v.x; q0 += v.x * v.x;
            s1 += v.y; q1 += v.y * v.y;
            s2 += v.z; q2 += v.z * v.z;
            s3 += v.w; q3 += v.w * v.w;
        }
    }
    atomicAdd(&ssum[tcol * 4 + 0], s0); atomicAdd(&ssq[tcol * 4 + 0], q0);
    atomicAdd(&ssum[tcol * 4 + 1], s1); atomicAdd(&ssq[tcol * 4 + 1], q1);
    atomicAdd(&ssum[tcol * 4 + 2], s2); atomicAdd(&ssq[tcol * 4 + 2], q2);
    atomicAdd(&ssum[tcol * 4 + 3], s3); atomicAdd(&ssq[tcol * 4 + 3], q3);
    __syncthreads();
    if (tid < D) {
        atomicAdd(&g_bsum[tid], (double)ssum[tid]);
        atomicAdd(&g_bsq[tid], (double)ssq[tid]);
    }
}

// BN batch stats -> per-column scale/shift; zero the accumulators for reuse
__global__ void k_bnp(const float* __restrict__ g, const float* __restrict__ b) {
    int c = threadIdx.x;
    double m = g_bsum[c] / (double)NN;
    double var = g_bsq[c] / (double)NN - m * m;
    float sc = g[c] * rsqrtf((float)var + BNEPS);
    g_scale[c] = sc;
    g_shift[c] = b[c] - (float)m * sc;
    g_bsum[c] = 0.0;
    g_bsq[c] = 0.0;
}

// h = relu(z2*scale + shift); optionally mirror to output buffer (last layer)
__global__ void k_hact(float* __restrict__ out_h) {
    int i = blockIdx.x * blockDim.x + threadIdx.x;
    if (i >= NN * D) return;
    int c = i & (D - 1);
    float hv = fmaxf(g_z2[i] * g_scale[c] + g_shift[c], 0.f);
    g_h[i] = hv;
    if (out_h) out_h[i] = hv;
}

// ---------------- pooling ---------------------------------------------------
__global__ void k_bounds(const int* __restrict__ batch) {
    int i = blockIdx.x * blockDim.x + threadIdx.x;
    if (i >= NN) return;
    if (i == 0) {
        g_starts[batch[0]] = 0;
        g_starts[NG] = NN;
    } else if (batch[i] != batch[i - 1]) {
        g_starts[batch[i]] = i;
    }
}

__global__ void k_pool(float* __restrict__ out) {
    __shared__ float sh[256];
    int g = blockIdx.x;
    int s = g_starts[g], e = g_starts[g + 1];
    int col = threadIdx.x & 127, half = threadIdx.x >> 7;
    float acc = 0.f;
    for (int r = s + half; r < e; r += 2) acc += g_h[r * D + col];
    sh[threadIdx.x] = acc;
    __syncthreads();
    if (half == 0) {
        float tot = sh[threadIdx.x] + sh[threadIdx.x + 128];
        int cnt = e - s;
        if (cnt < 1) cnt = 1;
        out[g * D + col] = tot / (float)cnt;
    }
}

// ---------------- launch -----------------------------------------------------
extern "C" void kernel_launch(void* const* d_in, const int* in_sizes, int n_in,
                              void* d_out, int out_size) {
    const int* feat_id = (const int*)d_in[0];
    const int* ei      = (const int*)d_in[1];
    const int* batch   = (const int*)d_in[2];
    const float* vpw   = (const float*)d_in[3];
    const float* vpb   = (const float*)d_in[4];
    const float* demb  = (const float*)d_in[5];
    const float* w1    = (const float*)d_in[6];
    const float* b1    = (const float*)d_in[7];
    const float* g1    = (const float*)d_in[8];
    const float* bb1   = (const float*)d_in[9];
    const float* w2    = (const float*)d_in[10];
    const float* b2    = (const float*)d_in[11];
    const float* g2    = (const float*)d_in[12];
    const float* bb2   = (const float*)d_in[13];

    float* out    = (float*)d_out;
    float* out_gf = out;           // [G, D]
    float* out_h  = out + NG * D;  // [N, D]

    const int* src = ei;        // edge_index[0]
    const int* dst = ei + NE;   // edge_index[1]

    // CSR build (by dst) + degree
    k_zero<<<(NN + 255) / 256, 256>>>();
    k_deg<<<(NE + 255) / 256, 256>>>(dst);
    k_scan<<<1, 1024>>>();
    k_fill<<<(NE + 255) / 256, 256>>>(src, dst);

    // node init
    k_init<<<(NN * 32 + 255) / 256, 256>>>(feat_id, (const float4*)vpw,
                                           (const float4*)vpb, (const float4*)demb);

    const int gemmGrid = (NN + 31) / 32;
    for (int l = 0; l < NL; l++) {
        k_agg<<<(NN * 32 + 255) / 256, 256>>>();
        // z1 = agg @ W1 + b1   (+BN1 stats)
        k_gemm<false, 0, 0><<<gemmGrid, 256>>>(w1 + l * D * D, b1 + l * D);
        k_bnp<<<1, D>>>(g1 + l * D, bb1 + l * D);
        // z2 = relu(bn1(z1)) @ W2 + b2   (+BN2 stats)
        k_gemm<true, 1, 1><<<gemmGrid, 256>>>(w2 + l * D * D, b2 + l * D);
        k_bnp<<<1, D>>>(g2 + l * D, bb2 + l * D);
        // h = relu(bn2(z2))
        k_hact<<<(NN * D + 255) / 256, 256>>>((l == NL - 1) ? out_h : (float*)0);
    }

    // global mean pool
    k_bounds<<<(NN + 255) / 256, 256>>>(batch);
    k_pool<<<NG, 256>>>(out_gf);
}